// round 2
// baseline (speedup 1.0000x reference)
#include <cuda_runtime.h>
#include <math.h>

#define NQ       16
#define BATCH    256
#define NL       4
#define NSTATES  65536
#define DIN      512
#define OUTD     10

// ---------------- scratch (device globals; no allocation allowed) ----------------
__device__ float2 g_state[BATCH * NSTATES];          // 128 MB statevector
__device__ float  g_T0[BATCH * 256];                 // product tables (low 8 bits)
__device__ float  g_T1[BATCH * 256];                 // product tables (high 8 bits)
__device__ float2 g_U[NL * NQ * 4];                  // per-layer per-qubit 2x2 complex
__device__ float2 g_M8[NL * 64];                     // fused 8x8 gate for qubits 0..2
__device__ float2 g_phase[NL * NSTATES];             // ZZ diagonal phase per layer
__device__ float  g_zpart[BATCH * 32 * 16];          // expectation partials

__device__ __forceinline__ float2 cmul(float2 a, float2 b) {
    return make_float2(a.x * b.x - a.y * b.y, a.x * b.y + a.y * b.x);
}

// shared-memory XOR swizzle (bank-conflict mitigation)
__device__ __forceinline__ int sw(int idx) { return idx ^ ((idx >> 5) & 31); }

// ---------------- prep: angles, product tables, gate matrices ----------------
__global__ void prep_kernel(const float* __restrict__ x,
                            const float* __restrict__ W_enc,
                            const float* __restrict__ b_enc,
                            const float* __restrict__ theta)
{
    __shared__ float partial[256];
    __shared__ float cs[NQ], ss[NQ];
    __shared__ float2 Ush[NL * NQ * 4];

    int b   = blockIdx.x;
    int tid = threadIdx.x;
    int q   = tid & 15;
    int seg = tid >> 4;

    // encoding dot products: thread (seg,q) sums 32 elements
    {
        float acc = 0.f;
        const float* xb = x + b * DIN;
        int d0 = seg * 32;
        #pragma unroll 8
        for (int d = d0; d < d0 + 32; d++)
            acc += xb[d] * W_enc[d * NQ + q];
        partial[tid] = acc;
    }
    __syncthreads();
    if (tid < NQ) {
        float s = b_enc[tid];
        #pragma unroll
        for (int g = 0; g < 16; g++) s += partial[g * 16 + tid];
        float ang = tanhf(s) * 3.14159265358979323846f;
        cs[tid] = cosf(0.5f * ang);
        ss[tid] = sinf(0.5f * ang);
    }
    __syncthreads();

    // product tables: amplitude(i) = T1[i>>8] * T0[i&255]
    {
        int m = tid;
        float p0 = 1.f, p1 = 1.f;
        #pragma unroll
        for (int k = 0; k < 8; k++) {
            int bit = (m >> k) & 1;
            p0 *= bit ? ss[15 - k] : cs[15 - k];       // global bit k   -> qubit 15-k
            p1 *= bit ? ss[7 - k]  : cs[7 - k];        // global bit k+8 -> qubit 7-k
        }
        g_T0[b * 256 + m] = p0;
        g_T1[b * 256 + m] = p1;
    }

    // block 0 additionally builds gate matrices
    if (b == 0) {
        if (tid < NL * NQ) {
            int l = tid >> 4, qq = tid & 15;
            const float* th = theta + (l * NQ + qq) * 3;
            float a0 = th[0], a1 = th[1], a2 = th[2];
            float ca = cosf(0.5f * a0), sa = sinf(0.5f * a0);
            float cb = cosf(0.5f * a1), sb = sinf(0.5f * a1);
            float cz = cosf(0.5f * a2), sz = sinf(0.5f * a2);
            float2 em = make_float2(cz, -sz);
            float2 ep = make_float2(cz,  sz);
            // R = RY @ RZ
            float2 r00 = make_float2( cb * em.x,  cb * em.y);
            float2 r01 = make_float2(-sb * ep.x, -sb * ep.y);
            float2 r10 = make_float2( sb * em.x,  sb * em.y);
            float2 r11 = make_float2( cb * ep.x,  cb * ep.y);
            // U = RX @ R,  RX = [[ca, -i sa], [-i sa, ca]]
            float2 u00 = make_float2(ca * r00.x + sa * r10.y, ca * r00.y - sa * r10.x);
            float2 u01 = make_float2(ca * r01.x + sa * r11.y, ca * r01.y - sa * r11.x);
            float2 u10 = make_float2(sa * r00.y + ca * r10.x, -sa * r00.x + ca * r10.y);
            float2 u11 = make_float2(sa * r01.y + ca * r11.x, -sa * r01.x + ca * r11.y);
            int base = tid * 4;
            Ush[base + 0] = u00; Ush[base + 1] = u01;
            Ush[base + 2] = u10; Ush[base + 3] = u11;
            g_U[base + 0] = u00; g_U[base + 1] = u01;
            g_U[base + 2] = u10; g_U[base + 3] = u11;
        }
        __syncthreads();
        // fused 8x8 matrix for qubits 0,1,2 (bits 15,14,13): j = i >> 13
        {
            int l = tid >> 6, rem = tid & 63, j = rem >> 3, jp = rem & 7;
            float2 A = Ush[(l * 16 + 0) * 4 + ((j >> 2) & 1) * 2 + ((jp >> 2) & 1)];
            float2 B = Ush[(l * 16 + 1) * 4 + ((j >> 1) & 1) * 2 + ((jp >> 1) & 1)];
            float2 C = Ush[(l * 16 + 2) * 4 + ((j      ) & 1) * 2 + ((jp      ) & 1)];
            g_M8[l * 64 + rem] = cmul(cmul(A, B), C);
        }
    }
}

// ---------------- ZZ phase tables ----------------
__global__ void phase_kernel(const float* __restrict__ phi)
{
    int gid = blockIdx.x * blockDim.x + threadIdx.x;  // 256*1024 = 4*65536
    int l = gid >> 16;
    int i = gid & 65535;
    float ang = 0.f;
    #pragma unroll
    for (int q = 0; q < 16; q++) {
        int b0 = (i >> (15 - q)) & 1;
        int b1 = (i >> (15 - ((q + 1) & 15))) & 1;
        float s = (b0 ^ b1) ? -1.f : 1.f;
        ang += __ldg(&phi[l * 16 + q]) * s;
    }
    float c, s;
    sincosf(0.5f * ang, &s, &c);
    g_phase[l * NSTATES + i] = make_float2(c, -s);   // exp(-0.5 i ang)
}

// ---------------- PassA: 13 gates on bits 0..12 (qubits 3..15) in shared ----------------
extern "C" __global__ void __launch_bounds__(512)
passA_kernel(int layer, int init)
{
    extern __shared__ float smem[];
    float* sre = smem;
    float* sim = smem + 8192;

    int t    = threadIdx.x;
    int tile = blockIdx.x;     // 0..7 -> bits 13..15 of global index
    int b    = blockIdx.y;
    int base = b * NSTATES + tile * 8192;

    if (init) {
        const float* T0 = g_T0 + b * 256;
        const float* T1 = g_T1 + b * 256;
        #pragma unroll
        for (int idx = t; idx < 8192; idx += 512) {
            int gi = (tile << 13) | idx;
            float amp = T1[gi >> 8] * T0[gi & 255];
            int p = sw(idx);
            sre[p] = amp;
            sim[p] = 0.f;
        }
    } else {
        #pragma unroll
        for (int idx = t; idx < 8192; idx += 512) {
            float2 v = g_state[base + idx];
            int p = sw(idx);
            sre[p] = v.x;
            sim[p] = v.y;
        }
    }

    const float2* U = g_U + layer * NQ * 4;
    float ar[16], ai[16];

    #pragma unroll
    for (int r = 0; r < 4; r++) {
        __syncthreads();
        // load this round's 16-amplitude subcube
        #pragma unroll
        for (int j = 0; j < 16; j++) {
            int idx;
            if (r < 3) {
                int lo = t & ((1 << (4 * r)) - 1);
                int hi = t >> (4 * r);
                idx = (hi << (4 * r + 4)) | (j << (4 * r)) | lo;
            } else {
                idx = ((j & 8) << 9) | (t << 3) | (j & 7);
            }
            int p = sw(idx);
            ar[j] = sre[p];
            ai[j] = sim[p];
        }

        if (r < 3) {
            #pragma unroll
            for (int v = 0; v < 4; v++) {
                int k = 4 * r + v;                 // global bit -> qubit 15-k
                float2 u00 = U[(15 - k) * 4 + 0];
                float2 u01 = U[(15 - k) * 4 + 1];
                float2 u10 = U[(15 - k) * 4 + 2];
                float2 u11 = U[(15 - k) * 4 + 3];
                #pragma unroll
                for (int m = 0; m < 16; m++) {
                    if (m & (1 << v)) continue;
                    int m1 = m | (1 << v);
                    float axr = ar[m],  axi = ai[m];
                    float bxr = ar[m1], bxi = ai[m1];
                    ar[m]  = u00.x * axr - u00.y * axi + u01.x * bxr - u01.y * bxi;
                    ai[m]  = u00.x * axi + u00.y * axr + u01.x * bxi + u01.y * bxr;
                    ar[m1] = u10.x * axr - u10.y * axi + u11.x * bxr - u11.y * bxi;
                    ai[m1] = u10.x * axi + u10.y * axr + u11.x * bxi + u11.y * bxr;
                }
            }
        } else {
            // single gate on bit 12 (qubit 3); pairs (m, m|8)
            float2 u00 = U[3 * 4 + 0];
            float2 u01 = U[3 * 4 + 1];
            float2 u10 = U[3 * 4 + 2];
            float2 u11 = U[3 * 4 + 3];
            #pragma unroll
            for (int m = 0; m < 8; m++) {
                int m1 = m | 8;
                float axr = ar[m],  axi = ai[m];
                float bxr = ar[m1], bxi = ai[m1];
                ar[m]  = u00.x * axr - u00.y * axi + u01.x * bxr - u01.y * bxi;
                ai[m]  = u00.x * axi + u00.y * axr + u01.x * bxi + u01.y * bxr;
                ar[m1] = u10.x * axr - u10.y * axi + u11.x * bxr - u11.y * bxi;
                ai[m1] = u10.x * axi + u10.y * axr + u11.x * bxi + u11.y * bxr;
            }
        }

        // store back (same per-thread locations; cross-thread sync at next round start)
        #pragma unroll
        for (int j = 0; j < 16; j++) {
            int idx;
            if (r < 3) {
                int lo = t & ((1 << (4 * r)) - 1);
                int hi = t >> (4 * r);
                idx = (hi << (4 * r + 4)) | (j << (4 * r)) | lo;
            } else {
                idx = ((j & 8) << 9) | (t << 3) | (j & 7);
            }
            int p = sw(idx);
            sre[p] = ar[j];
            sim[p] = ai[j];
        }
    }
    __syncthreads();

    #pragma unroll
    for (int idx = t; idx < 8192; idx += 512) {
        int p = sw(idx);
        g_state[base + idx] = make_float2(sre[p], sim[p]);
    }
}

// ---------------- PassB: fused 8x8 gate on bits 13..15 + ZZ phase (+ expectations) ----------------
extern "C" __global__ void __launch_bounds__(256)
passB_kernel(int layer, int last)
{
    __shared__ float2 M[64];
    __shared__ float  wsum[8][16];

    int t     = threadIdx.x;
    int chunk = blockIdx.x;   // 0..31
    int b     = blockIdx.y;

    if (t < 64) M[t] = g_M8[layer * 64 + t];
    __syncthreads();

    int r  = chunk * 256 + t;            // bits 0..12
    int sb = b * NSTATES;

    float2 a[8];
    #pragma unroll
    for (int j = 0; j < 8; j++) a[j] = g_state[sb + j * 8192 + r];

    float2 o[8];
    #pragma unroll
    for (int j = 0; j < 8; j++) {
        float orr = 0.f, oi = 0.f;
        #pragma unroll
        for (int jp = 0; jp < 8; jp++) {
            float2 m = M[j * 8 + jp];
            orr += m.x * a[jp].x - m.y * a[jp].y;
            oi  += m.x * a[jp].y + m.y * a[jp].x;
        }
        float2 ph = g_phase[layer * NSTATES + j * 8192 + r];
        o[j] = make_float2(orr * ph.x - oi * ph.y, orr * ph.y + oi * ph.x);
    }

    if (!last) {
        #pragma unroll
        for (int j = 0; j < 8; j++) g_state[sb + j * 8192 + r] = o[j];
    } else {
        // expectations: qubit q <-> bit 15-q. Bits 0..12 are fixed (= r) per thread.
        float p[8], ptot = 0.f;
        #pragma unroll
        for (int j = 0; j < 8; j++) {
            p[j] = o[j].x * o[j].x + o[j].y * o[j].y;
            ptot += p[j];
        }
        float acc[16];
        // q = 0,1,2 vary with j (bits 15,14,13)
        acc[0] = acc[1] = acc[2] = 0.f;
        #pragma unroll
        for (int j = 0; j < 8; j++) {
            acc[0] += ((j >> 2) & 1) ? -p[j] : p[j];
            acc[1] += ((j >> 1) & 1) ? -p[j] : p[j];
            acc[2] += ((j      ) & 1) ? -p[j] : p[j];
        }
        #pragma unroll
        for (int q = 3; q < 16; q++)
            acc[q] = (((r >> (15 - q)) & 1) ? -ptot : ptot);

        #pragma unroll
        for (int q = 0; q < 16; q++) {
            float v = acc[q];
            #pragma unroll
            for (int ofs = 16; ofs > 0; ofs >>= 1)
                v += __shfl_down_sync(0xffffffffu, v, ofs);
            if ((t & 31) == 0) wsum[t >> 5][q] = v;
        }
        __syncthreads();
        if (t < 16) {
            float v = 0.f;
            #pragma unroll
            for (int w = 0; w < 8; w++) v += wsum[w][t];
            g_zpart[(b * 32 + chunk) * 16 + t] = v;
        }
    }
}

// ---------------- final: deterministic reduce + MLP decoder ----------------
__global__ void final_kernel(const float* __restrict__ W1, const float* __restrict__ b1,
                             const float* __restrict__ W2, const float* __restrict__ b2,
                             float* __restrict__ out)
{
    int t = threadIdx.x;
    int warp = t >> 5, lane = t & 31;
    int b = blockIdx.x * 8 + warp;

    float z = 0.f;
    if (lane < 16) {
        #pragma unroll
        for (int c = 0; c < 32; c++) z += g_zpart[(b * 32 + c) * 16 + lane];
    }
    float h = b1[lane];
    #pragma unroll
    for (int q = 0; q < 16; q++) {
        float zq = __shfl_sync(0xffffffffu, z, q);
        h += zq * W1[q * 32 + lane];
    }
    h = fmaxf(h, 0.f);

    float o = (lane < OUTD) ? b2[lane] : 0.f;
    #pragma unroll
    for (int j = 0; j < 32; j++) {
        float hj = __shfl_sync(0xffffffffu, h, j);
        if (lane < OUTD) o += hj * W2[j * OUTD + lane];
    }
    if (lane < OUTD) out[b * OUTD + lane] = o;
}

// ---------------- launch ----------------
extern "C" void kernel_launch(void* const* d_in, const int* in_sizes, int n_in,
                              void* d_out, int out_size)
{
    const float* x     = (const float*)d_in[0];
    const float* W_enc = (const float*)d_in[1];
    const float* b_enc = (const float*)d_in[2];
    const float* theta = (const float*)d_in[3];
    const float* phi   = (const float*)d_in[4];
    const float* W1    = (const float*)d_in[5];
    const float* b1    = (const float*)d_in[6];
    const float* W2    = (const float*)d_in[7];
    const float* b2    = (const float*)d_in[8];
    float* out = (float*)d_out;

    cudaFuncSetAttribute((const void*)passA_kernel,
                         cudaFuncAttributeMaxDynamicSharedMemorySize, 65536);

    prep_kernel<<<256, 256>>>(x, W_enc, b_enc, theta);
    phase_kernel<<<256, 1024>>>(phi);

    for (int l = 0; l < NL; l++) {
        passA_kernel<<<dim3(8, 256), 512, 65536>>>(l, l == 0 ? 1 : 0);
        passB_kernel<<<dim3(32, 256), 256>>>(l, l == NL - 1 ? 1 : 0);
    }

    final_kernel<<<32, 256>>>(W1, b1, W2, b2, out);
}

// round 3
// speedup vs baseline: 1.0408x; 1.0408x over previous
#include <cuda_runtime.h>
#include <math.h>

#define NQ       16
#define BATCH    256
#define NL       4
#define NSTATES  65536
#define DIN      512
#define OUTD     10

typedef unsigned long long ull;

// ---------------- scratch ----------------
__device__ float2 g_state[BATCH * NSTATES];      // 128 MB statevector
__device__ float  g_T0[BATCH * 256];
__device__ float  g_T1[BATCH * 256];
__device__ float2 g_U[NL * NQ * 4];              // per-layer 2x2 gates
__device__ float2 g_M8v[NL * 4 * 64];            // fused 8x8 gate x phase variants [l][s3][s15][64]
__device__ float2 g_Pr[NL * 8192];               // r-local ZZ phase
__device__ float  g_zpart[BATCH * 16 * 16];

// ---------------- f32x2 helpers ----------------
__device__ __forceinline__ ull pk2(float lo, float hi) {
    ull r; asm("mov.b64 %0, {%1, %2};" : "=l"(r) : "f"(lo), "f"(hi)); return r;
}
__device__ __forceinline__ ull bc2(float v) {
    ull r; asm("mov.b64 %0, {%1, %1};" : "=l"(r) : "f"(v)); return r;
}
__device__ __forceinline__ void up2(ull v, float& lo, float& hi) {
    asm("mov.b64 {%0, %1}, %2;" : "=f"(lo), "=f"(hi) : "l"(v));
}
__device__ __forceinline__ ull f2fma(ull a, ull b, ull c) {
    ull d; asm("fma.rn.f32x2 %0, %1, %2, %3;" : "=l"(d) : "l"(a), "l"(b), "l"(c)); return d;
}
__device__ __forceinline__ ull f2mul(ull a, ull b) {
    ull d; asm("mul.rn.f32x2 %0, %1, %2;" : "=l"(d) : "l"(a), "l"(b)); return d;
}
__device__ __forceinline__ ull f2add(ull a, ull b) {
    ull d; asm("add.rn.f32x2 %0, %1, %2;" : "=l"(d) : "l"(a), "l"(b)); return d;
}
__device__ __forceinline__ float2 cmul(float2 a, float2 b) {
    return make_float2(a.x * b.x - a.y * b.y, a.x * b.y + a.y * b.x);
}
// 8-byte-element swizzle: distinct (e mod 16) within each half-warp for all access patterns
__device__ __forceinline__ int sw8(int i) { return i ^ ((i >> 4) & 15); }

// ---------------- prep ----------------
__global__ void prep_kernel(const float* __restrict__ x,
                            const float* __restrict__ W_enc,
                            const float* __restrict__ b_enc,
                            const float* __restrict__ theta,
                            const float* __restrict__ phi)
{
    __shared__ float partial[256];
    __shared__ float cs[NQ], ss[NQ];
    __shared__ float2 Ush[NL * NQ * 4];
    __shared__ float2 sM8[256];

    int b   = blockIdx.x;
    int tid = threadIdx.x;
    int q   = tid & 15;
    int seg = tid >> 4;

    {
        float acc = 0.f;
        const float* xb = x + b * DIN;
        int d0 = seg * 32;
        #pragma unroll 8
        for (int d = d0; d < d0 + 32; d++)
            acc += xb[d] * W_enc[d * NQ + q];
        partial[tid] = acc;
    }
    __syncthreads();
    if (tid < NQ) {
        float s = b_enc[tid];
        #pragma unroll
        for (int g = 0; g < 16; g++) s += partial[g * 16 + tid];
        float ang = tanhf(s) * 3.14159265358979323846f;
        cs[tid] = cosf(0.5f * ang);
        ss[tid] = sinf(0.5f * ang);
    }
    __syncthreads();

    {
        int m = tid;
        float p0 = 1.f, p1 = 1.f;
        #pragma unroll
        for (int k = 0; k < 8; k++) {
            int bit = (m >> k) & 1;
            p0 *= bit ? ss[15 - k] : cs[15 - k];
            p1 *= bit ? ss[7 - k]  : cs[7 - k];
        }
        g_T0[b * 256 + m] = p0;
        g_T1[b * 256 + m] = p1;
    }

    if (b == 0) {
        if (tid < NL * NQ) {
            int l = tid >> 4, qq = tid & 15;
            const float* th = theta + (l * NQ + qq) * 3;
            float a0 = th[0], a1 = th[1], a2 = th[2];
            float ca = cosf(0.5f * a0), sa = sinf(0.5f * a0);
            float cb = cosf(0.5f * a1), sb = sinf(0.5f * a1);
            float cz = cosf(0.5f * a2), sz = sinf(0.5f * a2);
            float2 em = make_float2(cz, -sz);
            float2 ep = make_float2(cz,  sz);
            float2 r00 = make_float2( cb * em.x,  cb * em.y);
            float2 r01 = make_float2(-sb * ep.x, -sb * ep.y);
            float2 r10 = make_float2( sb * em.x,  sb * em.y);
            float2 r11 = make_float2( cb * ep.x,  cb * ep.y);
            float2 u00 = make_float2(ca * r00.x + sa * r10.y, ca * r00.y - sa * r10.x);
            float2 u01 = make_float2(ca * r01.x + sa * r11.y, ca * r01.y - sa * r11.x);
            float2 u10 = make_float2(sa * r00.y + ca * r10.x, -sa * r00.x + ca * r10.y);
            float2 u11 = make_float2(sa * r01.y + ca * r11.x, -sa * r01.x + ca * r11.y);
            int base = tid * 4;
            Ush[base + 0] = u00; Ush[base + 1] = u01;
            Ush[base + 2] = u10; Ush[base + 3] = u11;
            g_U[base + 0] = u00; g_U[base + 1] = u01;
            g_U[base + 2] = u10; g_U[base + 3] = u11;
        }
        __syncthreads();
        // base fused 8x8 for qubits 0..2 (bits 15..13)
        {
            int l = tid >> 6, rem = tid & 63, j = rem >> 3, jp = rem & 7;
            float2 A = Ush[(l * 16 + 0) * 4 + ((j >> 2) & 1) * 2 + ((jp >> 2) & 1)];
            float2 B = Ush[(l * 16 + 1) * 4 + ((j >> 1) & 1) * 2 + ((jp >> 1) & 1)];
            float2 C = Ush[(l * 16 + 2) * 4 + ((j      ) & 1) * 2 + ((jp      ) & 1)];
            sM8[tid] = cmul(cmul(A, B), C);
        }
        __syncthreads();
        // fold j-local + cross ZZ phase into 4 variants of M8
        {
            int l = tid >> 6, rem = tid & 63, j = rem >> 3;
            float s0  = 1.f - 2.f * ((j >> 2) & 1);
            float s1  = 1.f - 2.f * ((j >> 1) & 1);
            float s2c = 1.f - 2.f * (j & 1);
            float p0 = phi[l * 16 + 0], p1 = phi[l * 16 + 1];
            float p2 = phi[l * 16 + 2], p15 = phi[l * 16 + 15];
            float angj = p0 * s0 * s1 + p1 * s1 * s2c;
            float2 m = sM8[tid];
            #pragma unroll
            for (int s3i = 0; s3i < 2; s3i++)
            #pragma unroll
            for (int s15i = 0; s15i < 2; s15i++) {
                float s3  = 1.f - 2.f * s3i;
                float s15 = 1.f - 2.f * s15i;
                float ang = angj + p2 * s2c * s3 + p15 * s15 * s0;
                float c, s;
                sincosf(0.5f * ang, &s, &c);
                float2 F = make_float2(c, -s);
                g_M8v[((l * 2 + s3i) * 2 + s15i) * 64 + rem] = cmul(F, m);
            }
        }
    }
}

// ---------------- Pr table: ZZ phase of r-internal edges ----------------
__global__ void pr_kernel(const float* __restrict__ phi)
{
    int gid = blockIdx.x * blockDim.x + threadIdx.x;   // 32768
    int l = gid >> 13;
    int r = gid & 8191;
    float ang = 0.f;
    #pragma unroll
    for (int kb = 1; kb <= 12; kb++) {
        float sA = 1.f - 2.f * ((r >> kb) & 1);
        float sB = 1.f - 2.f * ((r >> (kb - 1)) & 1);
        ang += __ldg(&phi[l * 16 + (15 - kb)]) * sA * sB;
    }
    float c, s;
    sincosf(0.5f * ang, &s, &c);
    g_Pr[l * 8192 + r] = make_float2(c, -s);
}

// ---------------- packed 2x2 gate on register subcube ----------------
template<int VB>
__device__ __forceinline__ void gate16(ull* ar, ull* ai, const float2* u)
{
    float2 u00 = u[0], u01 = u[1], u10 = u[2], u11 = u[3];
    ull U00x = bc2(u00.x), U00y = bc2(u00.y), N00y = bc2(-u00.y);
    ull U01x = bc2(u01.x), U01y = bc2(u01.y), N01y = bc2(-u01.y);
    ull U10x = bc2(u10.x), U10y = bc2(u10.y), N10y = bc2(-u10.y);
    ull U11x = bc2(u11.x), U11y = bc2(u11.y), N11y = bc2(-u11.y);
    #pragma unroll
    for (int m = 0; m < 16; m++) {
        if (m & (1 << VB)) continue;
        int m1 = m | (1 << VB);
        ull axr = ar[m],  axi = ai[m];
        ull bxr = ar[m1], bxi = ai[m1];
        ar[m]  = f2fma(U00x, axr, f2fma(N00y, axi, f2fma(U01x, bxr, f2mul(N01y, bxi))));
        ai[m]  = f2fma(U00x, axi, f2fma(U00y, axr, f2fma(U01x, bxi, f2mul(U01y, bxr))));
        ar[m1] = f2fma(U10x, axr, f2fma(N10y, axi, f2fma(U11x, bxr, f2mul(N11y, bxi))));
        ai[m1] = f2fma(U10x, axi, f2fma(U10y, axr, f2fma(U11x, bxi, f2mul(U11y, bxr))));
    }
}

// ---------------- PassA: gates on bits 0..12, packed across bit 13; x Pr epilogue ----------------
extern "C" __global__ void __launch_bounds__(512, 1)
passA_kernel(int layer, int init)
{
    extern __shared__ ull smem[];
    ull* sre = smem;
    ull* sim = smem + 8192;

    int t  = threadIdx.x;
    int tp = blockIdx.x;        // tile pair 0..3 (bits 14..15); pack dim = bit 13
    int b  = blockIdx.y;
    int base0 = b * NSTATES + tp * 16384;
    int base1 = base0 + 8192;

    if (init) {
        const float* T0 = g_T0 + b * 256;
        const float* T1 = g_T1 + b * 256;
        #pragma unroll
        for (int idx = t; idx < 8192; idx += 512) {
            int hi = idx >> 8, lo = idx & 255;
            float tl = T0[lo];
            float a0 = T1[(tp << 6) | hi] * tl;
            float a1 = T1[(tp << 6) | 32 | hi] * tl;
            int p = sw8(idx);
            sre[p] = pk2(a0, a1);
            sim[p] = 0ull;
        }
    } else {
        #pragma unroll
        for (int idx = t; idx < 8192; idx += 512) {
            float2 v0 = g_state[base0 + idx];
            float2 v1 = g_state[base1 + idx];
            int p = sw8(idx);
            sre[p] = pk2(v0.x, v1.x);
            sim[p] = pk2(v0.y, v1.y);
        }
    }

    const float2* U = g_U + layer * 64;
    ull ar[16], ai[16];

    #pragma unroll
    for (int rr = 0; rr < 4; rr++) {
        __syncthreads();
        #pragma unroll
        for (int j = 0; j < 16; j++) {
            int idx;
            if (rr < 3) {
                int lo = t & ((1 << (4 * rr)) - 1);
                int hi = t >> (4 * rr);
                idx = (hi << (4 * rr + 4)) | (j << (4 * rr)) | lo;
            } else {
                idx = ((j & 8) << 9) | (t << 3) | (j & 7);
            }
            int p = sw8(idx);
            ar[j] = sre[p];
            ai[j] = sim[p];
        }

        if (rr < 3) {
            gate16<0>(ar, ai, U + (15 - 4 * rr) * 4);
            gate16<1>(ar, ai, U + (14 - 4 * rr) * 4);
            gate16<2>(ar, ai, U + (13 - 4 * rr) * 4);
            gate16<3>(ar, ai, U + (12 - 4 * rr) * 4);
        } else {
            gate16<3>(ar, ai, U + 3 * 4);   // qubit 3 (bit 12)
        }

        #pragma unroll
        for (int j = 0; j < 16; j++) {
            int idx;
            if (rr < 3) {
                int lo = t & ((1 << (4 * rr)) - 1);
                int hi = t >> (4 * rr);
                idx = (hi << (4 * rr + 4)) | (j << (4 * rr)) | lo;
            } else {
                idx = ((j & 8) << 9) | (t << 3) | (j & 7);
            }
            int p = sw8(idx);
            sre[p] = ar[j];
            sim[p] = ai[j];
        }
    }
    __syncthreads();

    // epilogue: multiply by Pr (commutes with PassB's j-gates), write out
    const float2* Pr = g_Pr + layer * 8192;
    #pragma unroll
    for (int idx = t; idx < 8192; idx += 512) {
        int p = sw8(idx);
        ull re = sre[p], im = sim[p];
        float2 c = Pr[idx];
        ull CR = bc2(c.x), CI = bc2(c.y), NCI = bc2(-c.y);
        ull nre = f2fma(CR, re, f2mul(NCI, im));
        ull nim = f2fma(CR, im, f2mul(CI, re));
        float r0f, r1f, i0f, i1f;
        up2(nre, r0f, r1f);
        up2(nim, i0f, i1f);
        g_state[base0 + idx] = make_float2(r0f, i0f);
        g_state[base1 + idx] = make_float2(r1f, i1f);
    }
}

// ---------------- PassB: 8x8 gate (phase-folded variants) on bits 13..15, packed across r ----------------
extern "C" __global__ void __launch_bounds__(256)
passB_kernel(int layer, int last)
{
    __shared__ ull PX[2][64], PY[2][64], PNY[2][64];
    __shared__ float wsum[8][16];

    int t     = threadIdx.x;
    int chunk = blockIdx.x;    // 0..15
    int b     = blockIdx.y;

    if (t < 128) {
        int s3 = t >> 6, k = t & 63;
        float2 m0 = g_M8v[((layer * 2 + s3) * 2 + 0) * 64 + k];   // s15 = +1 (even r)
        float2 m1 = g_M8v[((layer * 2 + s3) * 2 + 1) * 64 + k];   // s15 = -1 (odd r)
        PX[s3][k]  = pk2(m0.x, m1.x);
        PY[s3][k]  = pk2(m0.y, m1.y);
        PNY[s3][k] = pk2(-m0.y, -m1.y);
    }
    __syncthreads();

    int r0 = chunk * 512 + 2 * t;     // even; thread handles r0, r0+1
    int s3 = chunk >> 3;              // bit 12 of r, constant per block
    int sb = b * NSTATES;

    ull are[8], aim[8];
    #pragma unroll
    for (int jp = 0; jp < 8; jp++) {
        float4 v = *reinterpret_cast<const float4*>(&g_state[sb + jp * 8192 + r0]);
        are[jp] = pk2(v.x, v.z);
        aim[jp] = pk2(v.y, v.w);
    }

    ull ore[8], oim[8];
    #pragma unroll
    for (int j = 0; j < 8; j++) {
        ull mx0 = PX[s3][j * 8], my0 = PY[s3][j * 8], nmy0 = PNY[s3][j * 8];
        ull orr = f2fma(nmy0, aim[0], f2mul(mx0, are[0]));
        ull oi  = f2fma(my0,  are[0], f2mul(mx0, aim[0]));
        #pragma unroll
        for (int jp = 1; jp < 8; jp++) {
            ull mx = PX[s3][j * 8 + jp], my = PY[s3][j * 8 + jp], nmy = PNY[s3][j * 8 + jp];
            orr = f2fma(mx, are[jp], orr);
            orr = f2fma(nmy, aim[jp], orr);
            oi  = f2fma(mx, aim[jp], oi);
            oi  = f2fma(my, are[jp], oi);
        }
        ore[j] = orr;
        oim[j] = oi;
    }

    if (!last) {
        #pragma unroll
        for (int j = 0; j < 8; j++) {
            float r0f, r1f, i0f, i1f;
            up2(ore[j], r0f, r1f);
            up2(oim[j], i0f, i1f);
            *reinterpret_cast<float4*>(&g_state[sb + j * 8192 + r0]) =
                make_float4(r0f, i0f, r1f, i1f);
        }
    } else {
        float p0[8], p1[8];
        float pt0 = 0.f, pt1 = 0.f;
        #pragma unroll
        for (int j = 0; j < 8; j++) {
            ull pj = f2fma(ore[j], ore[j], f2mul(oim[j], oim[j]));
            up2(pj, p0[j], p1[j]);
            pt0 += p0[j];
            pt1 += p1[j];
        }
        float acc[16];
        acc[0] = acc[1] = acc[2] = 0.f;
        #pragma unroll
        for (int j = 0; j < 8; j++) {
            float pj = p0[j] + p1[j];
            acc[0] += ((j >> 2) & 1) ? -pj : pj;
            acc[1] += ((j >> 1) & 1) ? -pj : pj;
            acc[2] += ((j     ) & 1) ? -pj : pj;
        }
        float pt = pt0 + pt1;
        #pragma unroll
        for (int q = 3; q < 15; q++)
            acc[q] = (((r0 >> (15 - q)) & 1) ? -pt : pt);
        acc[15] = pt0 - pt1;

        #pragma unroll
        for (int q = 0; q < 16; q++) {
            float v = acc[q];
            #pragma unroll
            for (int ofs = 16; ofs > 0; ofs >>= 1)
                v += __shfl_down_sync(0xffffffffu, v, ofs);
            if ((t & 31) == 0) wsum[t >> 5][q] = v;
        }
        __syncthreads();
        if (t < 16) {
            float v = 0.f;
            #pragma unroll
            for (int w = 0; w < 8; w++) v += wsum[w][t];
            g_zpart[(b * 16 + chunk) * 16 + t] = v;
        }
    }
}

// ---------------- final reduce + MLP ----------------
__global__ void final_kernel(const float* __restrict__ W1, const float* __restrict__ b1,
                             const float* __restrict__ W2, const float* __restrict__ b2,
                             float* __restrict__ out)
{
    int t = threadIdx.x;
    int warp = t >> 5, lane = t & 31;
    int b = blockIdx.x * 8 + warp;

    float z = 0.f;
    if (lane < 16) {
        #pragma unroll
        for (int c = 0; c < 16; c++) z += g_zpart[(b * 16 + c) * 16 + lane];
    }
    float h = b1[lane];
    #pragma unroll
    for (int q = 0; q < 16; q++) {
        float zq = __shfl_sync(0xffffffffu, z, q);
        h += zq * W1[q * 32 + lane];
    }
    h = fmaxf(h, 0.f);

    float o = (lane < OUTD) ? b2[lane] : 0.f;
    #pragma unroll
    for (int j = 0; j < 32; j++) {
        float hj = __shfl_sync(0xffffffffu, h, j);
        if (lane < OUTD) o += hj * W2[j * OUTD + lane];
    }
    if (lane < OUTD) out[b * OUTD + lane] = o;
}

// ---------------- launch ----------------
extern "C" void kernel_launch(void* const* d_in, const int* in_sizes, int n_in,
                              void* d_out, int out_size)
{
    const float* x     = (const float*)d_in[0];
    const float* W_enc = (const float*)d_in[1];
    const float* b_enc = (const float*)d_in[2];
    const float* theta = (const float*)d_in[3];
    const float* phi   = (const float*)d_in[4];
    const float* W1    = (const float*)d_in[5];
    const float* b1    = (const float*)d_in[6];
    const float* W2    = (const float*)d_in[7];
    const float* b2    = (const float*)d_in[8];
    float* out = (float*)d_out;

    cudaFuncSetAttribute((const void*)passA_kernel,
                         cudaFuncAttributeMaxDynamicSharedMemorySize, 131072);

    prep_kernel<<<256, 256>>>(x, W_enc, b_enc, theta, phi);
    pr_kernel<<<32, 1024>>>(phi);

    for (int l = 0; l < NL; l++) {
        passA_kernel<<<dim3(4, 256), 512, 131072>>>(l, l == 0 ? 1 : 0);
        passB_kernel<<<dim3(16, 256), 256>>>(l, l == NL - 1 ? 1 : 0);
    }

    final_kernel<<<32, 256>>>(W1, b1, W2, b2, out);
}

// round 4
// speedup vs baseline: 1.0753x; 1.0332x over previous
#include <cuda_runtime.h>
#include <math.h>

#define NQ       16
#define BATCH    256
#define NL       4
#define NSTATES  65536
#define DIN      512
#define OUTD     10

typedef unsigned long long ull;

// ---------------- scratch ----------------
__device__ float2 g_state[BATCH * NSTATES];      // 128 MB statevector
__device__ float  g_T0[BATCH * 256];
__device__ float  g_T1[BATCH * 256];
__device__ float2 g_U[NL * NQ * 4];              // per-layer 2x2 gates
__device__ float2 g_M8v[NL * 4 * 64];            // fused 8x8 gate x phase variants [l][s3][s15][64]
__device__ float2 g_Pr[NL * 8192];               // r-local ZZ phase
__device__ float  g_zpart[BATCH * 16 * 16];

// ---------------- f32x2 helpers ----------------
__device__ __forceinline__ ull pk2(float lo, float hi) {
    ull r; asm("mov.b64 %0, {%1, %2};" : "=l"(r) : "f"(lo), "f"(hi)); return r;
}
__device__ __forceinline__ ull bc2(float v) {
    ull r; asm("mov.b64 %0, {%1, %1};" : "=l"(r) : "f"(v)); return r;
}
__device__ __forceinline__ void up2(ull v, float& lo, float& hi) {
    asm("mov.b64 {%0, %1}, %2;" : "=f"(lo), "=f"(hi) : "l"(v));
}
__device__ __forceinline__ ull f2fma(ull a, ull b, ull c) {
    ull d; asm("fma.rn.f32x2 %0, %1, %2, %3;" : "=l"(d) : "l"(a), "l"(b), "l"(c)); return d;
}
__device__ __forceinline__ ull f2mul(ull a, ull b) {
    ull d; asm("mul.rn.f32x2 %0, %1, %2;" : "=l"(d) : "l"(a), "l"(b)); return d;
}
__device__ __forceinline__ ull f2add(ull a, ull b) {
    ull d; asm("add.rn.f32x2 %0, %1, %2;" : "=l"(d) : "l"(a), "l"(b)); return d;
}
__device__ __forceinline__ float2 cmul(float2 a, float2 b) {
    return make_float2(a.x * b.x - a.y * b.y, a.x * b.y + a.y * b.x);
}
// 8-byte-element swizzle: distinct (e mod 16) within each half-warp for all access patterns
__device__ __forceinline__ int sw8(int i) { return i ^ ((i >> 4) & 15); }

// ---------------- prep ----------------
__global__ void prep_kernel(const float* __restrict__ x,
                            const float* __restrict__ W_enc,
                            const float* __restrict__ b_enc,
                            const float* __restrict__ theta,
                            const float* __restrict__ phi)
{
    __shared__ float partial[256];
    __shared__ float cs[NQ], ss[NQ];
    __shared__ float2 Ush[NL * NQ * 4];
    __shared__ float2 sM8[256];

    int b   = blockIdx.x;
    int tid = threadIdx.x;
    int q   = tid & 15;
    int seg = tid >> 4;

    {
        float acc = 0.f;
        const float* xb = x + b * DIN;
        int d0 = seg * 32;
        #pragma unroll 8
        for (int d = d0; d < d0 + 32; d++)
            acc += xb[d] * W_enc[d * NQ + q];
        partial[tid] = acc;
    }
    __syncthreads();
    if (tid < NQ) {
        float s = b_enc[tid];
        #pragma unroll
        for (int g = 0; g < 16; g++) s += partial[g * 16 + tid];
        float ang = tanhf(s) * 3.14159265358979323846f;
        cs[tid] = cosf(0.5f * ang);
        ss[tid] = sinf(0.5f * ang);
    }
    __syncthreads();

    {
        int m = tid;
        float p0 = 1.f, p1 = 1.f;
        #pragma unroll
        for (int k = 0; k < 8; k++) {
            int bit = (m >> k) & 1;
            p0 *= bit ? ss[15 - k] : cs[15 - k];
            p1 *= bit ? ss[7 - k]  : cs[7 - k];
        }
        g_T0[b * 256 + m] = p0;
        g_T1[b * 256 + m] = p1;
    }

    if (b == 0) {
        if (tid < NL * NQ) {
            int l = tid >> 4, qq = tid & 15;
            const float* th = theta + (l * NQ + qq) * 3;
            float a0 = th[0], a1 = th[1], a2 = th[2];
            float ca = cosf(0.5f * a0), sa = sinf(0.5f * a0);
            float cb = cosf(0.5f * a1), sb = sinf(0.5f * a1);
            float cz = cosf(0.5f * a2), sz = sinf(0.5f * a2);
            float2 em = make_float2(cz, -sz);
            float2 ep = make_float2(cz,  sz);
            float2 r00 = make_float2( cb * em.x,  cb * em.y);
            float2 r01 = make_float2(-sb * ep.x, -sb * ep.y);
            float2 r10 = make_float2( sb * em.x,  sb * em.y);
            float2 r11 = make_float2( cb * ep.x,  cb * ep.y);
            float2 u00 = make_float2(ca * r00.x + sa * r10.y, ca * r00.y - sa * r10.x);
            float2 u01 = make_float2(ca * r01.x + sa * r11.y, ca * r01.y - sa * r11.x);
            float2 u10 = make_float2(sa * r00.y + ca * r10.x, -sa * r00.x + ca * r10.y);
            float2 u11 = make_float2(sa * r01.y + ca * r11.x, -sa * r01.x + ca * r11.y);
            int base = tid * 4;
            Ush[base + 0] = u00; Ush[base + 1] = u01;
            Ush[base + 2] = u10; Ush[base + 3] = u11;
            g_U[base + 0] = u00; g_U[base + 1] = u01;
            g_U[base + 2] = u10; g_U[base + 3] = u11;
        }
        __syncthreads();
        // base fused 8x8 for qubits 0..2 (bits 15..13)
        {
            int l = tid >> 6, rem = tid & 63, j = rem >> 3, jp = rem & 7;
            float2 A = Ush[(l * 16 + 0) * 4 + ((j >> 2) & 1) * 2 + ((jp >> 2) & 1)];
            float2 B = Ush[(l * 16 + 1) * 4 + ((j >> 1) & 1) * 2 + ((jp >> 1) & 1)];
            float2 C = Ush[(l * 16 + 2) * 4 + ((j      ) & 1) * 2 + ((jp      ) & 1)];
            sM8[tid] = cmul(cmul(A, B), C);
        }
        __syncthreads();
        // fold j-local + cross ZZ phase into 4 variants of M8
        {
            int l = tid >> 6, rem = tid & 63, j = rem >> 3;
            float s0  = 1.f - 2.f * ((j >> 2) & 1);
            float s1  = 1.f - 2.f * ((j >> 1) & 1);
            float s2c = 1.f - 2.f * (j & 1);
            float p0 = phi[l * 16 + 0], p1 = phi[l * 16 + 1];
            float p2 = phi[l * 16 + 2], p15 = phi[l * 16 + 15];
            float angj = p0 * s0 * s1 + p1 * s1 * s2c;
            float2 m = sM8[tid];
            #pragma unroll
            for (int s3i = 0; s3i < 2; s3i++)
            #pragma unroll
            for (int s15i = 0; s15i < 2; s15i++) {
                float s3  = 1.f - 2.f * s3i;
                float s15 = 1.f - 2.f * s15i;
                float ang = angj + p2 * s2c * s3 + p15 * s15 * s0;
                float c, s;
                sincosf(0.5f * ang, &s, &c);
                float2 F = make_float2(c, -s);
                g_M8v[((l * 2 + s3i) * 2 + s15i) * 64 + rem] = cmul(F, m);
            }
        }
    }
}

// ---------------- Pr table: ZZ phase of r-internal edges ----------------
__global__ void pr_kernel(const float* __restrict__ phi)
{
    int gid = blockIdx.x * blockDim.x + threadIdx.x;   // 32768
    int l = gid >> 13;
    int r = gid & 8191;
    float ang = 0.f;
    #pragma unroll
    for (int kb = 1; kb <= 12; kb++) {
        float sA = 1.f - 2.f * ((r >> kb) & 1);
        float sB = 1.f - 2.f * ((r >> (kb - 1)) & 1);
        ang += __ldg(&phi[l * 16 + (15 - kb)]) * sA * sB;
    }
    float c, s;
    sincosf(0.5f * ang, &s, &c);
    g_Pr[l * 8192 + r] = make_float2(c, -s);
}

// ---------------- packed 2x2 gate on register subcube ----------------
template<int VB>
__device__ __forceinline__ void gate16(ull* ar, ull* ai, const float2* u)
{
    float2 u00 = u[0], u01 = u[1], u10 = u[2], u11 = u[3];
    ull U00x = bc2(u00.x), U00y = bc2(u00.y), N00y = bc2(-u00.y);
    ull U01x = bc2(u01.x), U01y = bc2(u01.y), N01y = bc2(-u01.y);
    ull U10x = bc2(u10.x), U10y = bc2(u10.y), N10y = bc2(-u10.y);
    ull U11x = bc2(u11.x), U11y = bc2(u11.y), N11y = bc2(-u11.y);
    #pragma unroll
    for (int m = 0; m < 16; m++) {
        if (m & (1 << VB)) continue;
        int m1 = m | (1 << VB);
        ull axr = ar[m],  axi = ai[m];
        ull bxr = ar[m1], bxi = ai[m1];
        ar[m]  = f2fma(U00x, axr, f2fma(N00y, axi, f2fma(U01x, bxr, f2mul(N01y, bxi))));
        ai[m]  = f2fma(U00x, axi, f2fma(U00y, axr, f2fma(U01x, bxi, f2mul(U01y, bxr))));
        ar[m1] = f2fma(U10x, axr, f2fma(N10y, axi, f2fma(U11x, bxr, f2mul(N11y, bxi))));
        ai[m1] = f2fma(U10x, axi, f2fma(U10y, axr, f2fma(U11x, bxi, f2mul(U11y, bxr))));
    }
}

// ---------------- PassA: gates on bits 0..12, packed across bit 13; x Pr epilogue ----------------
extern "C" __global__ void __launch_bounds__(512, 1)
passA_kernel(int layer, int init)
{
    extern __shared__ ull smem[];
    ull* sre = smem;
    ull* sim = smem + 8192;

    int t  = threadIdx.x;
    int tp = blockIdx.x;        // tile pair 0..3 (bits 14..15); pack dim = bit 13
    int b  = blockIdx.y;
    int base0 = b * NSTATES + tp * 16384;
    int base1 = base0 + 8192;

    if (init) {
        const float* T0 = g_T0 + b * 256;
        const float* T1 = g_T1 + b * 256;
        #pragma unroll
        for (int idx = t; idx < 8192; idx += 512) {
            int hi = idx >> 8, lo = idx & 255;
            float tl = T0[lo];
            float a0 = T1[(tp << 6) | hi] * tl;
            float a1 = T1[(tp << 6) | 32 | hi] * tl;
            int p = sw8(idx);
            sre[p] = pk2(a0, a1);
            sim[p] = 0ull;
        }
    } else {
        #pragma unroll
        for (int idx = t; idx < 8192; idx += 512) {
            float2 v0 = g_state[base0 + idx];
            float2 v1 = g_state[base1 + idx];
            int p = sw8(idx);
            sre[p] = pk2(v0.x, v1.x);
            sim[p] = pk2(v0.y, v1.y);
        }
    }

    const float2* U = g_U + layer * 64;
    ull ar[16], ai[16];

    #pragma unroll
    for (int rr = 0; rr < 4; rr++) {
        __syncthreads();
        #pragma unroll
        for (int j = 0; j < 16; j++) {
            int idx;
            if (rr < 3) {
                int lo = t & ((1 << (4 * rr)) - 1);
                int hi = t >> (4 * rr);
                idx = (hi << (4 * rr + 4)) | (j << (4 * rr)) | lo;
            } else {
                idx = ((j & 8) << 9) | (t << 3) | (j & 7);
            }
            int p = sw8(idx);
            ar[j] = sre[p];
            ai[j] = sim[p];
        }

        if (rr < 3) {
            gate16<0>(ar, ai, U + (15 - 4 * rr) * 4);
            gate16<1>(ar, ai, U + (14 - 4 * rr) * 4);
            gate16<2>(ar, ai, U + (13 - 4 * rr) * 4);
            gate16<3>(ar, ai, U + (12 - 4 * rr) * 4);
        } else {
            gate16<3>(ar, ai, U + 3 * 4);   // qubit 3 (bit 12)
        }

        #pragma unroll
        for (int j = 0; j < 16; j++) {
            int idx;
            if (rr < 3) {
                int lo = t & ((1 << (4 * rr)) - 1);
                int hi = t >> (4 * rr);
                idx = (hi << (4 * rr + 4)) | (j << (4 * rr)) | lo;
            } else {
                idx = ((j & 8) << 9) | (t << 3) | (j & 7);
            }
            int p = sw8(idx);
            sre[p] = ar[j];
            sim[p] = ai[j];
        }
    }
    __syncthreads();

    // epilogue: multiply by Pr (commutes with PassB's j-gates), write out
    const float2* Pr = g_Pr + layer * 8192;
    #pragma unroll
    for (int idx = t; idx < 8192; idx += 512) {
        int p = sw8(idx);
        ull re = sre[p], im = sim[p];
        float2 c = Pr[idx];
        ull CR = bc2(c.x), CI = bc2(c.y), NCI = bc2(-c.y);
        ull nre = f2fma(CR, re, f2mul(NCI, im));
        ull nim = f2fma(CR, im, f2mul(CI, re));
        float r0f, r1f, i0f, i1f;
        up2(nre, r0f, r1f);
        up2(nim, i0f, i1f);
        g_state[base0 + idx] = make_float2(r0f, i0f);
        g_state[base1 + idx] = make_float2(r1f, i1f);
    }
}

// ---------------- PassB: 8x8 gate (phase-folded variants) on bits 13..15, packed across r ----------------
extern "C" __global__ void __launch_bounds__(256)
passB_kernel(int layer, int last)
{
    __shared__ ull PX[2][64], PY[2][64], PNY[2][64];
    __shared__ float wsum[8][16];

    int t     = threadIdx.x;
    int chunk = blockIdx.x;    // 0..15
    int b     = blockIdx.y;

    if (t < 128) {
        int s3 = t >> 6, k = t & 63;
        float2 m0 = g_M8v[((layer * 2 + s3) * 2 + 0) * 64 + k];   // s15 = +1 (even r)
        float2 m1 = g_M8v[((layer * 2 + s3) * 2 + 1) * 64 + k];   // s15 = -1 (odd r)
        PX[s3][k]  = pk2(m0.x, m1.x);
        PY[s3][k]  = pk2(m0.y, m1.y);
        PNY[s3][k] = pk2(-m0.y, -m1.y);
    }
    __syncthreads();

    int r0 = chunk * 512 + 2 * t;     // even; thread handles r0, r0+1
    int s3 = chunk >> 3;              // bit 12 of r, constant per block
    int sb = b * NSTATES;

    ull are[8], aim[8];
    #pragma unroll
    for (int jp = 0; jp < 8; jp++) {
        float4 v = *reinterpret_cast<const float4*>(&g_state[sb + jp * 8192 + r0]);
        are[jp] = pk2(v.x, v.z);
        aim[jp] = pk2(v.y, v.w);
    }

    ull ore[8], oim[8];
    #pragma unroll
    for (int j = 0; j < 8; j++) {
        ull mx0 = PX[s3][j * 8], my0 = PY[s3][j * 8], nmy0 = PNY[s3][j * 8];
        ull orr = f2fma(nmy0, aim[0], f2mul(mx0, are[0]));
        ull oi  = f2fma(my0,  are[0], f2mul(mx0, aim[0]));
        #pragma unroll
        for (int jp = 1; jp < 8; jp++) {
            ull mx = PX[s3][j * 8 + jp], my = PY[s3][j * 8 + jp], nmy = PNY[s3][j * 8 + jp];
            orr = f2fma(mx, are[jp], orr);
            orr = f2fma(nmy, aim[jp], orr);
            oi  = f2fma(mx, aim[jp], oi);
            oi  = f2fma(my, are[jp], oi);
        }
        ore[j] = orr;
        oim[j] = oi;
    }

    if (!last) {
        #pragma unroll
        for (int j = 0; j < 8; j++) {
            float r0f, r1f, i0f, i1f;
            up2(ore[j], r0f, r1f);
            up2(oim[j], i0f, i1f);
            *reinterpret_cast<float4*>(&g_state[sb + j * 8192 + r0]) =
                make_float4(r0f, i0f, r1f, i1f);
        }
    } else {
        float p0[8], p1[8];
        float pt0 = 0.f, pt1 = 0.f;
        #pragma unroll
        for (int j = 0; j < 8; j++) {
            ull pj = f2fma(ore[j], ore[j], f2mul(oim[j], oim[j]));
            up2(pj, p0[j], p1[j]);
            pt0 += p0[j];
            pt1 += p1[j];
        }
        float acc[16];
        acc[0] = acc[1] = acc[2] = 0.f;
        #pragma unroll
        for (int j = 0; j < 8; j++) {
            float pj = p0[j] + p1[j];
            acc[0] += ((j >> 2) & 1) ? -pj : pj;
            acc[1] += ((j >> 1) & 1) ? -pj : pj;
            acc[2] += ((j     ) & 1) ? -pj : pj;
        }
        float pt = pt0 + pt1;
        #pragma unroll
        for (int q = 3; q < 15; q++)
            acc[q] = (((r0 >> (15 - q)) & 1) ? -pt : pt);
        acc[15] = pt0 - pt1;

        #pragma unroll
        for (int q = 0; q < 16; q++) {
            float v = acc[q];
            #pragma unroll
            for (int ofs = 16; ofs > 0; ofs >>= 1)
                v += __shfl_down_sync(0xffffffffu, v, ofs);
            if ((t & 31) == 0) wsum[t >> 5][q] = v;
        }
        __syncthreads();
        if (t < 16) {
            float v = 0.f;
            #pragma unroll
            for (int w = 0; w < 8; w++) v += wsum[w][t];
            g_zpart[(b * 16 + chunk) * 16 + t] = v;
        }
    }
}

// ---------------- final reduce + MLP ----------------
__global__ void final_kernel(const float* __restrict__ W1, const float* __restrict__ b1,
                             const float* __restrict__ W2, const float* __restrict__ b2,
                             float* __restrict__ out)
{
    int t = threadIdx.x;
    int warp = t >> 5, lane = t & 31;
    int b = blockIdx.x * 8 + warp;

    float z = 0.f;
    if (lane < 16) {
        #pragma unroll
        for (int c = 0; c < 16; c++) z += g_zpart[(b * 16 + c) * 16 + lane];
    }
    float h = b1[lane];
    #pragma unroll
    for (int q = 0; q < 16; q++) {
        float zq = __shfl_sync(0xffffffffu, z, q);
        h += zq * W1[q * 32 + lane];
    }
    h = fmaxf(h, 0.f);

    float o = (lane < OUTD) ? b2[lane] : 0.f;
    #pragma unroll
    for (int j = 0; j < 32; j++) {
        float hj = __shfl_sync(0xffffffffu, h, j);
        if (lane < OUTD) o += hj * W2[j * OUTD + lane];
    }
    if (lane < OUTD) out[b * OUTD + lane] = o;
}

// ---------------- launch ----------------
extern "C" void kernel_launch(void* const* d_in, const int* in_sizes, int n_in,
                              void* d_out, int out_size)
{
    const float* x     = (const float*)d_in[0];
    const float* W_enc = (const float*)d_in[1];
    const float* b_enc = (const float*)d_in[2];
    const float* theta = (const float*)d_in[3];
    const float* phi   = (const float*)d_in[4];
    const float* W1    = (const float*)d_in[5];
    const float* b1    = (const float*)d_in[6];
    const float* W2    = (const float*)d_in[7];
    const float* b2    = (const float*)d_in[8];
    float* out = (float*)d_out;

    cudaFuncSetAttribute((const void*)passA_kernel,
                         cudaFuncAttributeMaxDynamicSharedMemorySize, 131072);

    prep_kernel<<<256, 256>>>(x, W_enc, b_enc, theta, phi);
    pr_kernel<<<32, 1024>>>(phi);

    for (int l = 0; l < NL; l++) {
        passA_kernel<<<dim3(4, 256), 512, 131072>>>(l, l == 0 ? 1 : 0);
        passB_kernel<<<dim3(16, 256), 256>>>(l, l == NL - 1 ? 1 : 0);
    }

    final_kernel<<<32, 256>>>(W1, b1, W2, b2, out);
}

// round 5
// speedup vs baseline: 1.0778x; 1.0023x over previous
#include <cuda_runtime.h>
#include <math.h>

#define NQ       16
#define BATCH    256
#define NL       4
#define NSTATES  65536
#define DIN      512
#define OUTD     10

typedef unsigned long long ull;

// ---------------- scratch ----------------
__device__ float2 g_state[BATCH * NSTATES];      // 128 MB statevector
__device__ float  g_T0[BATCH * 256];
__device__ float  g_T1[BATCH * 256];
__device__ float2 g_U[NL * NQ * 4];              // per-layer 2x2 gates
__device__ float2 g_M8v[NL * 4 * 64];            // fused 8x8 gate x phase variants [l][s3][s15][64]
__device__ float2 g_Pr[NL * 8192];               // r-local ZZ phase
__device__ float  g_zpart[BATCH * 16 * 16];

// ---------------- f32x2 helpers ----------------
__device__ __forceinline__ ull pk2(float lo, float hi) {
    ull r; asm("mov.b64 %0, {%1, %2};" : "=l"(r) : "f"(lo), "f"(hi)); return r;
}
__device__ __forceinline__ ull bc2(float v) {
    ull r; asm("mov.b64 %0, {%1, %1};" : "=l"(r) : "f"(v)); return r;
}
__device__ __forceinline__ void up2(ull v, float& lo, float& hi) {
    asm("mov.b64 {%0, %1}, %2;" : "=f"(lo), "=f"(hi) : "l"(v));
}
__device__ __forceinline__ ull f2fma(ull a, ull b, ull c) {
    ull d; asm("fma.rn.f32x2 %0, %1, %2, %3;" : "=l"(d) : "l"(a), "l"(b), "l"(c)); return d;
}
__device__ __forceinline__ ull f2mul(ull a, ull b) {
    ull d; asm("mul.rn.f32x2 %0, %1, %2;" : "=l"(d) : "l"(a), "l"(b)); return d;
}
__device__ __forceinline__ ull f2add(ull a, ull b) {
    ull d; asm("add.rn.f32x2 %0, %1, %2;" : "=l"(d) : "l"(a), "l"(b)); return d;
}
__device__ __forceinline__ float2 cmul(float2 a, float2 b) {
    return make_float2(a.x * b.x - a.y * b.y, a.x * b.y + a.y * b.x);
}
// 8-byte-element swizzle: distinct (e mod 16) within each half-warp for all access patterns
__device__ __forceinline__ int sw8(int i) { return i ^ ((i >> 4) & 15); }

// ---------------- prep ----------------
__global__ void prep_kernel(const float* __restrict__ x,
                            const float* __restrict__ W_enc,
                            const float* __restrict__ b_enc,
                            const float* __restrict__ theta,
                            const float* __restrict__ phi)
{
    __shared__ float partial[256];
    __shared__ float cs[NQ], ss[NQ];
    __shared__ float2 Ush[NL * NQ * 4];
    __shared__ float2 sM8[256];

    int b   = blockIdx.x;
    int tid = threadIdx.x;
    int q   = tid & 15;
    int seg = tid >> 4;

    {
        float acc = 0.f;
        const float* xb = x + b * DIN;
        int d0 = seg * 32;
        #pragma unroll 8
        for (int d = d0; d < d0 + 32; d++)
            acc += xb[d] * W_enc[d * NQ + q];
        partial[tid] = acc;
    }
    __syncthreads();
    if (tid < NQ) {
        float s = b_enc[tid];
        #pragma unroll
        for (int g = 0; g < 16; g++) s += partial[g * 16 + tid];
        float ang = tanhf(s) * 3.14159265358979323846f;
        cs[tid] = cosf(0.5f * ang);
        ss[tid] = sinf(0.5f * ang);
    }
    __syncthreads();

    {
        int m = tid;
        float p0 = 1.f, p1 = 1.f;
        #pragma unroll
        for (int k = 0; k < 8; k++) {
            int bit = (m >> k) & 1;
            p0 *= bit ? ss[15 - k] : cs[15 - k];
            p1 *= bit ? ss[7 - k]  : cs[7 - k];
        }
        g_T0[b * 256 + m] = p0;
        g_T1[b * 256 + m] = p1;
    }

    if (b == 0) {
        if (tid < NL * NQ) {
            int l = tid >> 4, qq = tid & 15;
            const float* th = theta + (l * NQ + qq) * 3;
            float a0 = th[0], a1 = th[1], a2 = th[2];
            float ca = cosf(0.5f * a0), sa = sinf(0.5f * a0);
            float cb = cosf(0.5f * a1), sb = sinf(0.5f * a1);
            float cz = cosf(0.5f * a2), sz = sinf(0.5f * a2);
            float2 em = make_float2(cz, -sz);
            float2 ep = make_float2(cz,  sz);
            float2 r00 = make_float2( cb * em.x,  cb * em.y);
            float2 r01 = make_float2(-sb * ep.x, -sb * ep.y);
            float2 r10 = make_float2( sb * em.x,  sb * em.y);
            float2 r11 = make_float2( cb * ep.x,  cb * ep.y);
            float2 u00 = make_float2(ca * r00.x + sa * r10.y, ca * r00.y - sa * r10.x);
            float2 u01 = make_float2(ca * r01.x + sa * r11.y, ca * r01.y - sa * r11.x);
            float2 u10 = make_float2(sa * r00.y + ca * r10.x, -sa * r00.x + ca * r10.y);
            float2 u11 = make_float2(sa * r01.y + ca * r11.x, -sa * r01.x + ca * r11.y);
            int base = tid * 4;
            Ush[base + 0] = u00; Ush[base + 1] = u01;
            Ush[base + 2] = u10; Ush[base + 3] = u11;
            g_U[base + 0] = u00; g_U[base + 1] = u01;
            g_U[base + 2] = u10; g_U[base + 3] = u11;
        }
        __syncthreads();
        // base fused 8x8 for qubits 0..2 (bits 15..13)
        {
            int l = tid >> 6, rem = tid & 63, j = rem >> 3, jp = rem & 7;
            float2 A = Ush[(l * 16 + 0) * 4 + ((j >> 2) & 1) * 2 + ((jp >> 2) & 1)];
            float2 B = Ush[(l * 16 + 1) * 4 + ((j >> 1) & 1) * 2 + ((jp >> 1) & 1)];
            float2 C = Ush[(l * 16 + 2) * 4 + ((j      ) & 1) * 2 + ((jp      ) & 1)];
            sM8[tid] = cmul(cmul(A, B), C);
        }
        __syncthreads();
        // fold j-local + cross ZZ phase into 4 variants of M8
        {
            int l = tid >> 6, rem = tid & 63, j = rem >> 3;
            float s0  = 1.f - 2.f * ((j >> 2) & 1);
            float s1  = 1.f - 2.f * ((j >> 1) & 1);
            float s2c = 1.f - 2.f * (j & 1);
            float p0 = phi[l * 16 + 0], p1 = phi[l * 16 + 1];
            float p2 = phi[l * 16 + 2], p15 = phi[l * 16 + 15];
            float angj = p0 * s0 * s1 + p1 * s1 * s2c;
            float2 m = sM8[tid];
            #pragma unroll
            for (int s3i = 0; s3i < 2; s3i++)
            #pragma unroll
            for (int s15i = 0; s15i < 2; s15i++) {
                float s3  = 1.f - 2.f * s3i;
                float s15 = 1.f - 2.f * s15i;
                float ang = angj + p2 * s2c * s3 + p15 * s15 * s0;
                float c, s;
                sincosf(0.5f * ang, &s, &c);
                float2 F = make_float2(c, -s);
                g_M8v[((l * 2 + s3i) * 2 + s15i) * 64 + rem] = cmul(F, m);
            }
        }
    }
}

// ---------------- Pr table: ZZ phase of r-internal edges ----------------
__global__ void pr_kernel(const float* __restrict__ phi)
{
    int gid = blockIdx.x * blockDim.x + threadIdx.x;   // 32768
    int l = gid >> 13;
    int r = gid & 8191;
    float ang = 0.f;
    #pragma unroll
    for (int kb = 1; kb <= 12; kb++) {
        float sA = 1.f - 2.f * ((r >> kb) & 1);
        float sB = 1.f - 2.f * ((r >> (kb - 1)) & 1);
        ang += __ldg(&phi[l * 16 + (15 - kb)]) * sA * sB;
    }
    float c, s;
    sincosf(0.5f * ang, &s, &c);
    g_Pr[l * 8192 + r] = make_float2(c, -s);
}

// ---------------- packed 2x2 gate on register subcube ----------------
template<int VB>
__device__ __forceinline__ void gate16(ull* ar, ull* ai, const float2* u)
{
    float2 u00 = u[0], u01 = u[1], u10 = u[2], u11 = u[3];
    ull U00x = bc2(u00.x), U00y = bc2(u00.y), N00y = bc2(-u00.y);
    ull U01x = bc2(u01.x), U01y = bc2(u01.y), N01y = bc2(-u01.y);
    ull U10x = bc2(u10.x), U10y = bc2(u10.y), N10y = bc2(-u10.y);
    ull U11x = bc2(u11.x), U11y = bc2(u11.y), N11y = bc2(-u11.y);
    #pragma unroll
    for (int m = 0; m < 16; m++) {
        if (m & (1 << VB)) continue;
        int m1 = m | (1 << VB);
        ull axr = ar[m],  axi = ai[m];
        ull bxr = ar[m1], bxi = ai[m1];
        ar[m]  = f2fma(U00x, axr, f2fma(N00y, axi, f2fma(U01x, bxr, f2mul(N01y, bxi))));
        ai[m]  = f2fma(U00x, axi, f2fma(U00y, axr, f2fma(U01x, bxi, f2mul(U01y, bxr))));
        ar[m1] = f2fma(U10x, axr, f2fma(N10y, axi, f2fma(U11x, bxr, f2mul(N11y, bxi))));
        ai[m1] = f2fma(U10x, axi, f2fma(U10y, axr, f2fma(U11x, bxi, f2mul(U11y, bxr))));
    }
}

// ---------------- PassA: gates on bits 0..12, packed across bit 13; x Pr epilogue ----------------
extern "C" __global__ void __launch_bounds__(512, 1)
passA_kernel(int layer, int init)
{
    extern __shared__ ull smem[];
    ull* sre = smem;
    ull* sim = smem + 8192;

    int t  = threadIdx.x;
    int tp = blockIdx.x;        // tile pair 0..3 (bits 14..15); pack dim = bit 13
    int b  = blockIdx.y;
    int base0 = b * NSTATES + tp * 16384;
    int base1 = base0 + 8192;

    if (init) {
        const float* T0 = g_T0 + b * 256;
        const float* T1 = g_T1 + b * 256;
        #pragma unroll
        for (int idx = t; idx < 8192; idx += 512) {
            int hi = idx >> 8, lo = idx & 255;
            float tl = T0[lo];
            float a0 = T1[(tp << 6) | hi] * tl;
            float a1 = T1[(tp << 6) | 32 | hi] * tl;
            int p = sw8(idx);
            sre[p] = pk2(a0, a1);
            sim[p] = 0ull;
        }
    } else {
        #pragma unroll
        for (int idx = t; idx < 8192; idx += 512) {
            float2 v0 = g_state[base0 + idx];
            float2 v1 = g_state[base1 + idx];
            int p = sw8(idx);
            sre[p] = pk2(v0.x, v1.x);
            sim[p] = pk2(v0.y, v1.y);
        }
    }

    const float2* U = g_U + layer * 64;
    ull ar[16], ai[16];

    #pragma unroll
    for (int rr = 0; rr < 4; rr++) {
        __syncthreads();
        #pragma unroll
        for (int j = 0; j < 16; j++) {
            int idx;
            if (rr < 3) {
                int lo = t & ((1 << (4 * rr)) - 1);
                int hi = t >> (4 * rr);
                idx = (hi << (4 * rr + 4)) | (j << (4 * rr)) | lo;
            } else {
                idx = ((j & 8) << 9) | (t << 3) | (j & 7);
            }
            int p = sw8(idx);
            ar[j] = sre[p];
            ai[j] = sim[p];
        }

        if (rr < 3) {
            gate16<0>(ar, ai, U + (15 - 4 * rr) * 4);
            gate16<1>(ar, ai, U + (14 - 4 * rr) * 4);
            gate16<2>(ar, ai, U + (13 - 4 * rr) * 4);
            gate16<3>(ar, ai, U + (12 - 4 * rr) * 4);
        } else {
            gate16<3>(ar, ai, U + 3 * 4);   // qubit 3 (bit 12)
        }

        #pragma unroll
        for (int j = 0; j < 16; j++) {
            int idx;
            if (rr < 3) {
                int lo = t & ((1 << (4 * rr)) - 1);
                int hi = t >> (4 * rr);
                idx = (hi << (4 * rr + 4)) | (j << (4 * rr)) | lo;
            } else {
                idx = ((j & 8) << 9) | (t << 3) | (j & 7);
            }
            int p = sw8(idx);
            sre[p] = ar[j];
            sim[p] = ai[j];
        }
    }
    __syncthreads();

    // epilogue: multiply by Pr (commutes with PassB's j-gates), write out
    const float2* Pr = g_Pr + layer * 8192;
    #pragma unroll
    for (int idx = t; idx < 8192; idx += 512) {
        int p = sw8(idx);
        ull re = sre[p], im = sim[p];
        float2 c = Pr[idx];
        ull CR = bc2(c.x), CI = bc2(c.y), NCI = bc2(-c.y);
        ull nre = f2fma(CR, re, f2mul(NCI, im));
        ull nim = f2fma(CR, im, f2mul(CI, re));
        float r0f, r1f, i0f, i1f;
        up2(nre, r0f, r1f);
        up2(nim, i0f, i1f);
        g_state[base0 + idx] = make_float2(r0f, i0f);
        g_state[base1 + idx] = make_float2(r1f, i1f);
    }
}

// ---------------- PassB: 8x8 gate (phase-folded variants) on bits 13..15, packed across r ----------------
extern "C" __global__ void __launch_bounds__(256)
passB_kernel(int layer, int last)
{
    __shared__ ull PX[2][64], PY[2][64], PNY[2][64];
    __shared__ float wsum[8][16];

    int t     = threadIdx.x;
    int chunk = blockIdx.x;    // 0..15
    int b     = blockIdx.y;

    if (t < 128) {
        int s3 = t >> 6, k = t & 63;
        float2 m0 = g_M8v[((layer * 2 + s3) * 2 + 0) * 64 + k];   // s15 = +1 (even r)
        float2 m1 = g_M8v[((layer * 2 + s3) * 2 + 1) * 64 + k];   // s15 = -1 (odd r)
        PX[s3][k]  = pk2(m0.x, m1.x);
        PY[s3][k]  = pk2(m0.y, m1.y);
        PNY[s3][k] = pk2(-m0.y, -m1.y);
    }
    __syncthreads();

    int r0 = chunk * 512 + 2 * t;     // even; thread handles r0, r0+1
    int s3 = chunk >> 3;              // bit 12 of r, constant per block
    int sb = b * NSTATES;

    ull are[8], aim[8];
    #pragma unroll
    for (int jp = 0; jp < 8; jp++) {
        float4 v = *reinterpret_cast<const float4*>(&g_state[sb + jp * 8192 + r0]);
        are[jp] = pk2(v.x, v.z);
        aim[jp] = pk2(v.y, v.w);
    }

    ull ore[8], oim[8];
    #pragma unroll
    for (int j = 0; j < 8; j++) {
        ull mx0 = PX[s3][j * 8], my0 = PY[s3][j * 8], nmy0 = PNY[s3][j * 8];
        ull orr = f2fma(nmy0, aim[0], f2mul(mx0, are[0]));
        ull oi  = f2fma(my0,  are[0], f2mul(mx0, aim[0]));
        #pragma unroll
        for (int jp = 1; jp < 8; jp++) {
            ull mx = PX[s3][j * 8 + jp], my = PY[s3][j * 8 + jp], nmy = PNY[s3][j * 8 + jp];
            orr = f2fma(mx, are[jp], orr);
            orr = f2fma(nmy, aim[jp], orr);
            oi  = f2fma(mx, aim[jp], oi);
            oi  = f2fma(my, are[jp], oi);
        }
        ore[j] = orr;
        oim[j] = oi;
    }

    if (!last) {
        #pragma unroll
        for (int j = 0; j < 8; j++) {
            float r0f, r1f, i0f, i1f;
            up2(ore[j], r0f, r1f);
            up2(oim[j], i0f, i1f);
            *reinterpret_cast<float4*>(&g_state[sb + j * 8192 + r0]) =
                make_float4(r0f, i0f, r1f, i1f);
        }
    } else {
        float p0[8], p1[8];
        float pt0 = 0.f, pt1 = 0.f;
        #pragma unroll
        for (int j = 0; j < 8; j++) {
            ull pj = f2fma(ore[j], ore[j], f2mul(oim[j], oim[j]));
            up2(pj, p0[j], p1[j]);
            pt0 += p0[j];
            pt1 += p1[j];
        }
        float acc[16];
        acc[0] = acc[1] = acc[2] = 0.f;
        #pragma unroll
        for (int j = 0; j < 8; j++) {
            float pj = p0[j] + p1[j];
            acc[0] += ((j >> 2) & 1) ? -pj : pj;
            acc[1] += ((j >> 1) & 1) ? -pj : pj;
            acc[2] += ((j     ) & 1) ? -pj : pj;
        }
        float pt = pt0 + pt1;
        #pragma unroll
        for (int q = 3; q < 15; q++)
            acc[q] = (((r0 >> (15 - q)) & 1) ? -pt : pt);
        acc[15] = pt0 - pt1;

        #pragma unroll
        for (int q = 0; q < 16; q++) {
            float v = acc[q];
            #pragma unroll
            for (int ofs = 16; ofs > 0; ofs >>= 1)
                v += __shfl_down_sync(0xffffffffu, v, ofs);
            if ((t & 31) == 0) wsum[t >> 5][q] = v;
        }
        __syncthreads();
        if (t < 16) {
            float v = 0.f;
            #pragma unroll
            for (int w = 0; w < 8; w++) v += wsum[w][t];
            g_zpart[(b * 16 + chunk) * 16 + t] = v;
        }
    }
}

// ---------------- final reduce + MLP ----------------
__global__ void final_kernel(const float* __restrict__ W1, const float* __restrict__ b1,
                             const float* __restrict__ W2, const float* __restrict__ b2,
                             float* __restrict__ out)
{
    int t = threadIdx.x;
    int warp = t >> 5, lane = t & 31;
    int b = blockIdx.x * 8 + warp;

    float z = 0.f;
    if (lane < 16) {
        #pragma unroll
        for (int c = 0; c < 16; c++) z += g_zpart[(b * 16 + c) * 16 + lane];
    }
    float h = b1[lane];
    #pragma unroll
    for (int q = 0; q < 16; q++) {
        float zq = __shfl_sync(0xffffffffu, z, q);
        h += zq * W1[q * 32 + lane];
    }
    h = fmaxf(h, 0.f);

    float o = (lane < OUTD) ? b2[lane] : 0.f;
    #pragma unroll
    for (int j = 0; j < 32; j++) {
        float hj = __shfl_sync(0xffffffffu, h, j);
        if (lane < OUTD) o += hj * W2[j * OUTD + lane];
    }
    if (lane < OUTD) out[b * OUTD + lane] = o;
}

// ---------------- launch ----------------
extern "C" void kernel_launch(void* const* d_in, const int* in_sizes, int n_in,
                              void* d_out, int out_size)
{
    const float* x     = (const float*)d_in[0];
    const float* W_enc = (const float*)d_in[1];
    const float* b_enc = (const float*)d_in[2];
    const float* theta = (const float*)d_in[3];
    const float* phi   = (const float*)d_in[4];
    const float* W1    = (const float*)d_in[5];
    const float* b1    = (const float*)d_in[6];
    const float* W2    = (const float*)d_in[7];
    const float* b2    = (const float*)d_in[8];
    float* out = (float*)d_out;

    cudaFuncSetAttribute((const void*)passA_kernel,
                         cudaFuncAttributeMaxDynamicSharedMemorySize, 131072);

    prep_kernel<<<256, 256>>>(x, W_enc, b_enc, theta, phi);
    pr_kernel<<<32, 1024>>>(phi);

    for (int l = 0; l < NL; l++) {
        passA_kernel<<<dim3(4, 256), 512, 131072>>>(l, l == 0 ? 1 : 0);
        passB_kernel<<<dim3(16, 256), 256>>>(l, l == NL - 1 ? 1 : 0);
    }

    final_kernel<<<32, 256>>>(W1, b1, W2, b2, out);
}

// round 6
// speedup vs baseline: 1.0935x; 1.0146x over previous
#include <cuda_runtime.h>
#include <math.h>

#define NQ       16
#define BATCH    256
#define NL       4
#define DIN      512
#define OUTD     10

typedef unsigned long long ull;

// ---------------- scratch (SoA state, packed across amp bit 0 = qubit 15) ----------------
__device__ ull   g_re[BATCH * 32768];        // 64 MB re pairs
__device__ ull   g_im[BATCH * 32768];        // 64 MB im pairs
__device__ ull   g_T0u[BATCH * 128];         // product table, amp low-8 bits (float pairs)
__device__ float g_T1[BATCH * 256];          // product table, amp high-8 bits
__device__ ull   g_Upk[NL * 12 * 12];        // broadcast-packed 2x2 gates, qubits 3..14
__device__ ull   g_Lq[NL * 6];               // lane gate (qubit 15) packed consts
__device__ float2 g_M8v[NL * 4 * 64];        // fused 8x8 (qubits 0,1,2) x phase variants [l][s3][s15]
__device__ ull   g_PrRe[NL * 4096], g_PrIm[NL * 4096], g_PrImN[NL * 4096];
__device__ float g_zpart[BATCH * 16 * 16];

// ---------------- f32x2 helpers ----------------
__device__ __forceinline__ ull pk2(float lo, float hi) {
    ull r; asm("mov.b64 %0, {%1, %2};" : "=l"(r) : "f"(lo), "f"(hi)); return r;
}
__device__ __forceinline__ ull bc2(float v) {
    ull r; asm("mov.b64 %0, {%1, %1};" : "=l"(r) : "f"(v)); return r;
}
__device__ __forceinline__ void up2(ull v, float& lo, float& hi) {
    asm("mov.b64 {%0, %1}, %2;" : "=f"(lo), "=f"(hi) : "l"(v));
}
__device__ __forceinline__ ull f2fma(ull a, ull b, ull c) {
    ull d; asm("fma.rn.f32x2 %0, %1, %2, %3;" : "=l"(d) : "l"(a), "l"(b), "l"(c)); return d;
}
__device__ __forceinline__ ull f2mul(ull a, ull b) {
    ull d; asm("mul.rn.f32x2 %0, %1, %2;" : "=l"(d) : "l"(a), "l"(b)); return d;
}
__device__ __forceinline__ ull swap2(ull v) {
    float lo, hi; up2(v, lo, hi); return pk2(hi, lo);
}
__device__ __forceinline__ float2 cmulh(float2 a, float2 b) {
    return make_float2(a.x * b.x - a.y * b.y, a.x * b.y + a.y * b.x);
}
// smem swizzle on 8B elements; conflict-free for all access patterns used (verified per round)
__device__ __forceinline__ int swz(int i) { return i ^ ((i >> 3) & 15); }

// ---------------- prep ----------------
__global__ void prep_kernel(const float* __restrict__ x,
                            const float* __restrict__ W_enc,
                            const float* __restrict__ b_enc,
                            const float* __restrict__ theta,
                            const float* __restrict__ phi)
{
    __shared__ float partial[256];
    __shared__ float cs[NQ], ss[NQ];
    __shared__ float2 Ush[NL * NQ * 4];
    __shared__ float2 sM8[256];

    int b   = blockIdx.x;
    int tid = threadIdx.x;
    int q   = tid & 15;
    int seg = tid >> 4;

    {
        float acc = 0.f;
        const float* xb = x + b * DIN;
        int d0 = seg * 32;
        #pragma unroll 8
        for (int d = d0; d < d0 + 32; d++)
            acc += xb[d] * W_enc[d * NQ + q];
        partial[tid] = acc;
    }
    __syncthreads();
    if (tid < NQ) {
        float s = b_enc[tid];
        #pragma unroll
        for (int g = 0; g < 16; g++) s += partial[g * 16 + tid];
        float ang = tanhf(s) * 3.14159265358979323846f;
        cs[tid] = cosf(0.5f * ang);
        ss[tid] = sinf(0.5f * ang);
    }
    __syncthreads();

    // product tables over amplitude bits (amp bit k -> qubit 15-k)
    {
        int m = tid;
        float p0 = 1.f, p1 = 1.f;
        #pragma unroll
        for (int k = 0; k < 8; k++) {
            int bit = (m >> k) & 1;
            p0 *= bit ? ss[15 - k] : cs[15 - k];
            p1 *= bit ? ss[7 - k]  : cs[7 - k];
        }
        ((float*)g_T0u)[b * 256 + m] = p0;
        g_T1[b * 256 + m] = p1;
    }

    if (b == 0) {
        if (tid < NL * NQ) {
            int l = tid >> 4, qq = tid & 15;
            const float* th = theta + (l * NQ + qq) * 3;
            float a0 = th[0], a1 = th[1], a2 = th[2];
            float ca = cosf(0.5f * a0), sa = sinf(0.5f * a0);
            float cb = cosf(0.5f * a1), sb = sinf(0.5f * a1);
            float cz = cosf(0.5f * a2), sz = sinf(0.5f * a2);
            float2 em = make_float2(cz, -sz);
            float2 ep = make_float2(cz,  sz);
            float2 r00 = make_float2( cb * em.x,  cb * em.y);
            float2 r01 = make_float2(-sb * ep.x, -sb * ep.y);
            float2 r10 = make_float2( sb * em.x,  sb * em.y);
            float2 r11 = make_float2( cb * ep.x,  cb * ep.y);
            float2 u00 = make_float2(ca * r00.x + sa * r10.y, ca * r00.y - sa * r10.x);
            float2 u01 = make_float2(ca * r01.x + sa * r11.y, ca * r01.y - sa * r11.x);
            float2 u10 = make_float2(sa * r00.y + ca * r10.x, -sa * r00.x + ca * r10.y);
            float2 u11 = make_float2(sa * r01.y + ca * r11.x, -sa * r01.x + ca * r11.y);
            int base = tid * 4;
            Ush[base + 0] = u00; Ush[base + 1] = u01;
            Ush[base + 2] = u10; Ush[base + 3] = u11;
        }
        __syncthreads();

        // broadcast-packed passA gate constants for qubits 3..14 (g = qubit-3)
        for (int k = tid; k < NL * 144; k += 256) {
            int l = k / 144, rem = k % 144, g = rem / 12, e = rem % 12;
            int j2 = e / 3, kind = e % 3;
            float2 u = Ush[(l * 16 + (g + 3)) * 4 + j2];
            float v = (kind == 0) ? u.x : ((kind == 1) ? u.y : -u.y);
            g_Upk[k] = bc2(v);
        }

        // lane gate (qubit 15) packed constants
        if (tid < NL) {
            int l = tid;
            float2 u00 = Ush[(l * 16 + 15) * 4 + 0];
            float2 u01 = Ush[(l * 16 + 15) * 4 + 1];
            float2 u10 = Ush[(l * 16 + 15) * 4 + 2];
            float2 u11 = Ush[(l * 16 + 15) * 4 + 3];
            g_Lq[l * 6 + 0] = pk2(u00.x, u11.x);
            g_Lq[l * 6 + 1] = pk2(u01.x, u10.x);
            g_Lq[l * 6 + 2] = pk2(-u00.y, -u11.y);
            g_Lq[l * 6 + 3] = pk2(-u01.y, -u10.y);
            g_Lq[l * 6 + 4] = pk2(u00.y, u11.y);
            g_Lq[l * 6 + 5] = pk2(u01.y, u10.y);
        }

        // base fused 8x8 for qubits 0,1,2  (j bit2=q0, bit1=q1, bit0=q2)
        {
            int l = tid >> 6, rem = tid & 63, j = rem >> 3, jp = rem & 7;
            float2 A = Ush[(l * 16 + 0) * 4 + ((j >> 2) & 1) * 2 + ((jp >> 2) & 1)];
            float2 B = Ush[(l * 16 + 1) * 4 + ((j >> 1) & 1) * 2 + ((jp >> 1) & 1)];
            float2 C = Ush[(l * 16 + 2) * 4 + ((j      ) & 1) * 2 + ((jp      ) & 1)];
            sM8[tid] = cmulh(cmulh(A, B), C);
        }
        __syncthreads();
        // fold phase edges (0,1),(1,2),(2,3),(15,0) into 4 variants (s3 = qubit-3 spin, s15 = lane)
        {
            int l = tid >> 6, rem = tid & 63, j = rem >> 3;
            float s0  = 1.f - 2.f * ((j >> 2) & 1);
            float s1  = 1.f - 2.f * ((j >> 1) & 1);
            float s2c = 1.f - 2.f * (j & 1);
            float p0 = phi[l * 16 + 0], p1 = phi[l * 16 + 1];
            float p2 = phi[l * 16 + 2], p15 = phi[l * 16 + 15];
            float angj = p0 * s0 * s1 + p1 * s1 * s2c;
            float2 m = sM8[tid];
            #pragma unroll
            for (int s3i = 0; s3i < 2; s3i++)
            #pragma unroll
            for (int s15i = 0; s15i < 2; s15i++) {
                float s3  = 1.f - 2.f * s3i;
                float s15 = 1.f - 2.f * s15i;
                float ang = angj + p2 * s2c * s3 + p15 * s15 * s0;
                float c, s;
                sincosf(0.5f * ang, &s, &c);
                float2 F = make_float2(c, -s);
                g_M8v[((l * 2 + s3i) * 2 + s15i) * 64 + rem] = cmulh(F, m);
            }
        }
    }
}

// ---------------- Pr tables: ZZ edges (3,4)..(13,14) + lane-split edge (14,15) ----------------
__global__ void pr_kernel(const float* __restrict__ phi)
{
    int gid = blockIdx.x * blockDim.x + threadIdx.x;   // NL*4096
    int l = gid >> 12;
    int p = gid & 4095;
    float ang = 0.f;
    #pragma unroll
    for (int bb = 0; bb < 11; bb++) {
        float sA = 1.f - 2.f * ((p >> (bb + 1)) & 1);
        float sB = 1.f - 2.f * ((p >> bb) & 1);
        ang += __ldg(&phi[l * 16 + 13 - bb]) * sA * sB;   // edge (13-bb, 14-bb)
    }
    float e14 = __ldg(&phi[l * 16 + 14]) * (1.f - 2.f * (p & 1));  // edge (14,15)
    float a0 = ang + e14, a1 = ang - e14;                // lane 0: s15=+1, lane 1: s15=-1
    float c0, s0, c1, s1;
    sincosf(0.5f * a0, &s0, &c0);
    sincosf(0.5f * a1, &s1, &c1);
    g_PrRe[l * 4096 + p]  = pk2(c0, c1);
    g_PrIm[l * 4096 + p]  = pk2(-s0, -s1);
    g_PrImN[l * 4096 + p] = pk2(s0, s1);
}

// ---------------- packed 2x2 gate on 8-value register subcube ----------------
template<int VB>
__device__ __forceinline__ void gate8(ull* ar, ull* ai, const ull* u)
{
    ull u00x = u[0], u00y = u[1],  u00yn = u[2];
    ull u01x = u[3], u01y = u[4],  u01yn = u[5];
    ull u10x = u[6], u10y = u[7],  u10yn = u[8];
    ull u11x = u[9], u11y = u[10], u11yn = u[11];
    #pragma unroll
    for (int m = 0; m < 8; m++) {
        if (m & (1 << VB)) continue;
        int m1 = m | (1 << VB);
        ull axr = ar[m],  axi = ai[m];
        ull bxr = ar[m1], bxi = ai[m1];
        ar[m]  = f2fma(u00x, axr, f2fma(u00yn, axi, f2fma(u01x, bxr, f2mul(u01yn, bxi))));
        ai[m]  = f2fma(u00x, axi, f2fma(u00y,  axr, f2fma(u01x, bxi, f2mul(u01y,  bxr))));
        ar[m1] = f2fma(u10x, axr, f2fma(u10yn, axi, f2fma(u11x, bxr, f2mul(u11yn, bxi))));
        ai[m1] = f2fma(u10x, axi, f2fma(u10y,  axr, f2fma(u11x, bxi, f2mul(u11y,  bxr))));
    }
}

// ---------------- PassA: lane gate (q15) + 12 gates (q3..14) + Pr phase ----------------
extern "C" __global__ void __launch_bounds__(512, 1)
passA_kernel(int layer, int init)
{
    extern __shared__ ull smem[];
    ull* sre = smem;
    ull* sim = smem + 8192;
    __shared__ ull sU[144];
    __shared__ ull sLq[6];

    int t    = threadIdx.x;
    int tile = blockIdx.x;     // p bits 13,14 (qubits 1,0) - untouched here
    int b    = blockIdx.y;
    int base = b * 32768 + tile * 8192;

    if (t < 144) sU[t] = g_Upk[layer * 144 + t];
    if (t < 6)   sLq[t] = g_Lq[layer * 6 + t];

    if (init) {
        #pragma unroll
        for (int k = 0; k < 16; k++) {
            int p = k * 512 + t;
            float t1 = g_T1[b * 256 + (tile << 6) + (p >> 7)];
            ull  t0 = g_T0u[b * 128 + (p & 127)];
            int s = swz(p);
            sre[s] = f2mul(bc2(t1), t0);
            sim[s] = 0ull;
        }
    } else {
        #pragma unroll
        for (int k = 0; k < 16; k++) {
            int p = k * 512 + t;
            int s = swz(p);
            sre[s] = g_re[base + p];
            sim[s] = g_im[base + p];
        }
    }

    #pragma unroll
    for (int rr = 0; rr < 4; rr++) {
        __syncthreads();
        #pragma unroll
        for (int set = 0; set < 2; set++) {
            ull ar[8], ai[8];
            int s  = 3 * rr;
            int lo = t & ((1 << s) - 1);
            int hi = t >> s;
            int pre = (set << 12) | (hi << (s + 3)) | lo;
            int idxs[8];
            #pragma unroll
            for (int j = 0; j < 8; j++) idxs[j] = pre | (j << s);

            #pragma unroll
            for (int j = 0; j < 8; j++) {
                int sp = swz(idxs[j]);
                ar[j] = sre[sp];
                ai[j] = sim[sp];
            }

            if (rr == 0) {
                // lane gate: qubit 15 (packing lane)
                ull P1 = sLq[0], P2 = sLq[1], P3 = sLq[2], P4 = sLq[3], P5 = sLq[4], P6 = sLq[5];
                #pragma unroll
                for (int m = 0; m < 8; m++) {
                    ull sar = swap2(ar[m]), sai = swap2(ai[m]);
                    ull nr = f2fma(P1, ar[m], f2fma(P2, sar, f2fma(P3, ai[m], f2mul(P4, sai))));
                    ull ni = f2fma(P1, ai[m], f2fma(P2, sai, f2fma(P5, ar[m], f2mul(P6, sar))));
                    ar[m] = nr; ai[m] = ni;
                }
            }

            // gates on p bits 3rr, 3rr+1, 3rr+2  (qubit 14 - bit; sU index g = 11 - bit)
            gate8<0>(ar, ai, &sU[(11 - 3 * rr) * 12]);
            gate8<1>(ar, ai, &sU[(10 - 3 * rr) * 12]);
            gate8<2>(ar, ai, &sU[( 9 - 3 * rr) * 12]);

            #pragma unroll
            for (int j = 0; j < 8; j++) {
                int sp = swz(idxs[j]);
                sre[sp] = ar[j];
                sim[sp] = ai[j];
            }
        }
    }
    __syncthreads();

    // epilogue: Pr phase (independent of p bit 12) + writeout
    const ull* PR  = g_PrRe  + layer * 4096;
    const ull* PI  = g_PrIm  + layer * 4096;
    const ull* PIN = g_PrImN + layer * 4096;
    #pragma unroll
    for (int k = 0; k < 16; k++) {
        int p = k * 512 + t;
        int s = swz(p);
        ull re = sre[s], im = sim[s];
        int pr = p & 4095;
        ull cr = PR[pr], ci = PI[pr], cin = PIN[pr];
        ull nre = f2fma(cr, re, f2mul(cin, im));
        ull nim = f2fma(cr, im, f2mul(ci, re));
        g_re[base + p] = nre;
        g_im[base + p] = nim;
    }
}

// ---------------- PassB: 8x8 gate on qubits 0,1,2 (+ folded phases, + expectations) ----------------
extern "C" __global__ void __launch_bounds__(256)
passB_kernel(int layer, int last)
{
    __shared__ ull PX[2][64], PY[2][64], PNY[2][64];
    __shared__ float wsum[8][16];

    int t = threadIdx.x;
    int b = blockIdx.y;

    if (t < 128) {
        int s3 = t >> 6, k = t & 63;
        float2 m0 = g_M8v[((layer * 2 + s3) * 2 + 0) * 64 + k];   // lane 0: s15=+1
        float2 m1 = g_M8v[((layer * 2 + s3) * 2 + 1) * 64 + k];   // lane 1: s15=-1
        PX[s3][k]  = pk2(m0.x, m1.x);
        PY[s3][k]  = pk2(m0.y, m1.y);
        PNY[s3][k] = pk2(-m0.y, -m1.y);
    }
    __syncthreads();

    int r  = blockIdx.x * 256 + t;     // p bits 0..11
    int s3 = (r >> 11) & 1;            // qubit-3 spin variant
    int gb = b * 32768;

    ull are[8], aim[8];
    #pragma unroll
    for (int jp = 0; jp < 8; jp++) {
        are[jp] = g_re[gb + jp * 4096 + r];
        aim[jp] = g_im[gb + jp * 4096 + r];
    }

    ull ore[8], oim[8];
    #pragma unroll
    for (int j = 0; j < 8; j++) {
        ull mx0 = PX[s3][j * 8], my0 = PY[s3][j * 8], nmy0 = PNY[s3][j * 8];
        ull orr = f2fma(nmy0, aim[0], f2mul(mx0, are[0]));
        ull oi  = f2fma(my0,  are[0], f2mul(mx0, aim[0]));
        #pragma unroll
        for (int jp = 1; jp < 8; jp++) {
            ull mx = PX[s3][j * 8 + jp], my = PY[s3][j * 8 + jp], nmy = PNY[s3][j * 8 + jp];
            orr = f2fma(mx, are[jp], orr);
            orr = f2fma(nmy, aim[jp], orr);
            oi  = f2fma(mx, aim[jp], oi);
            oi  = f2fma(my, are[jp], oi);
        }
        ore[j] = orr;
        oim[j] = oi;
    }

    if (!last) {
        #pragma unroll
        for (int j = 0; j < 8; j++) {
            g_re[gb + j * 4096 + r] = ore[j];
            g_im[gb + j * 4096 + r] = oim[j];
        }
    } else {
        // expectations: amp i = (p<<1)|lane, p = j*4096 + r
        float ptl0 = 0.f, ptl1 = 0.f, a0 = 0.f, a1 = 0.f, a2 = 0.f;
        #pragma unroll
        for (int j = 0; j < 8; j++) {
            ull pp = f2fma(ore[j], ore[j], f2mul(oim[j], oim[j]));
            float l0, l1; up2(pp, l0, l1);
            float pj = l0 + l1;
            ptl0 += l0; ptl1 += l1;
            a0 += ((j >> 2) & 1) ? -pj : pj;   // qubit 0 = j bit2
            a1 += ((j >> 1) & 1) ? -pj : pj;   // qubit 1 = j bit1
            a2 += ( j       & 1) ? -pj : pj;   // qubit 2 = j bit0
        }
        float pt = ptl0 + ptl1;
        float acc[16];
        acc[0] = a0; acc[1] = a1; acc[2] = a2;
        #pragma unroll
        for (int q = 3; q < 15; q++)
            acc[q] = ((r >> (14 - q)) & 1) ? -pt : pt;   // qubit q = r bit (14-q)
        acc[15] = ptl0 - ptl1;                            // lane spin

        #pragma unroll
        for (int q = 0; q < 16; q++) {
            float v = acc[q];
            #pragma unroll
            for (int ofs = 16; ofs > 0; ofs >>= 1)
                v += __shfl_down_sync(0xffffffffu, v, ofs);
            if ((t & 31) == 0) wsum[t >> 5][q] = v;
        }
        __syncthreads();
        if (t < 16) {
            float v = 0.f;
            #pragma unroll
            for (int w = 0; w < 8; w++) v += wsum[w][t];
            g_zpart[(b * 16 + blockIdx.x) * 16 + t] = v;
        }
    }
}

// ---------------- final reduce + MLP ----------------
__global__ void final_kernel(const float* __restrict__ W1, const float* __restrict__ b1,
                             const float* __restrict__ W2, const float* __restrict__ b2,
                             float* __restrict__ out)
{
    int t = threadIdx.x;
    int warp = t >> 5, lane = t & 31;
    int b = blockIdx.x * 8 + warp;

    float z = 0.f;
    if (lane < 16) {
        #pragma unroll
        for (int c = 0; c < 16; c++) z += g_zpart[(b * 16 + c) * 16 + lane];
    }
    float h = b1[lane];
    #pragma unroll
    for (int q = 0; q < 16; q++) {
        float zq = __shfl_sync(0xffffffffu, z, q);
        h += zq * W1[q * 32 + lane];
    }
    h = fmaxf(h, 0.f);

    float o = (lane < OUTD) ? b2[lane] : 0.f;
    #pragma unroll
    for (int j = 0; j < 32; j++) {
        float hj = __shfl_sync(0xffffffffu, h, j);
        if (lane < OUTD) o += hj * W2[j * OUTD + lane];
    }
    if (lane < OUTD) out[b * OUTD + lane] = o;
}

// ---------------- launch ----------------
extern "C" void kernel_launch(void* const* d_in, const int* in_sizes, int n_in,
                              void* d_out, int out_size)
{
    const float* x     = (const float*)d_in[0];
    const float* W_enc = (const float*)d_in[1];
    const float* b_enc = (const float*)d_in[2];
    const float* theta = (const float*)d_in[3];
    const float* phi   = (const float*)d_in[4];
    const float* W1    = (const float*)d_in[5];
    const float* b1    = (const float*)d_in[6];
    const float* W2    = (const float*)d_in[7];
    const float* b2    = (const float*)d_in[8];
    float* out = (float*)d_out;

    cudaFuncSetAttribute((const void*)passA_kernel,
                         cudaFuncAttributeMaxDynamicSharedMemorySize, 131072);

    prep_kernel<<<256, 256>>>(x, W_enc, b_enc, theta, phi);
    pr_kernel<<<16, 1024>>>(phi);

    for (int l = 0; l < NL; l++) {
        passA_kernel<<<dim3(4, 256), 512, 131072>>>(l, l == 0 ? 1 : 0);
        passB_kernel<<<dim3(16, 256), 256>>>(l, l == NL - 1 ? 1 : 0);
    }

    final_kernel<<<32, 256>>>(W1, b1, W2, b2, out);
}